// round 2
// baseline (speedup 1.0000x reference)
#include <cuda_runtime.h>
#include <math_constants.h>

// Sampler: B=256 rows, V=128000 vocab.
// inputs: logits [B,V] f32, temperatures [B] f32, uniform_noise [B,V] f32
// output: [tokens (B floats)] ++ [probs (B*V floats)]

#define NTHREADS 1024
#define BB 256
#define VV 128000

struct AMax { float v; int i; };

__device__ __forceinline__ void amax_upd(AMax& a, float v, int i) {
    // strict > keeps the LOWEST index on ties (indices visited in ascending order)
    if (v > a.v) { a.v = v; a.i = i; }
}

__device__ __forceinline__ void amax_comb(AMax& a, float v, int i) {
    if (v > a.v || (v == a.v && i < a.i)) { a.v = v; a.i = i; }
}

__device__ __forceinline__ AMax warp_amax(AMax a) {
    #pragma unroll
    for (int off = 16; off; off >>= 1) {
        float v = __shfl_xor_sync(0xffffffffu, a.v, off);
        int   i = __shfl_xor_sync(0xffffffffu, a.i, off);
        amax_comb(a, v, i);
    }
    return a;
}

__device__ __forceinline__ void ms_comb(float& m, float& s, float m2, float s2) {
    float mn = fmaxf(m, m2);
    // exp(-inf) == 0 handles empty halves
    s = s * __expf(m - mn) + s2 * __expf(m2 - mn);
    m = mn;
}

__device__ __forceinline__ void warp_ms(float& m, float& s) {
    #pragma unroll
    for (int off = 16; off; off >>= 1) {
        float m2 = __shfl_xor_sync(0xffffffffu, m, off);
        float s2 = __shfl_xor_sync(0xffffffffu, s, off);
        ms_comb(m, s, m2, s2);
    }
}

__global__ void __launch_bounds__(NTHREADS)
sampler_kernel(const float* __restrict__ logits,
               const float* __restrict__ temps,
               const float* __restrict__ noise,
               float* __restrict__ out)
{
    const int b = blockIdx.x;
    const int tid = threadIdx.x;
    const int lane = tid & 31;
    const int wid = tid >> 5;

    const float t = temps[b];
    const float safe_t = (t == 0.0f) ? 1.0f : t;

    const float4* __restrict__ lrow = (const float4*)(logits + (size_t)b * VV);
    const float4* __restrict__ nrow = (const float4*)(noise  + (size_t)b * VV);
    float4* __restrict__ prow = (float4*)(out + BB + (size_t)b * VV);

    AMax greedy; greedy.v = -CUDART_INF_F; greedy.i = 0x7fffffff;
    AMax samp;   samp.v   = -CUDART_INF_F; samp.i   = 0x7fffffff;
    float m = -CUDART_INF_F;  // online softmax max of scaled
    float s = 0.0f;           // online softmax sum

    const int nvec = VV / 4;  // 32000
    for (int j = tid; j < nvec; j += NTHREADS) {
        float4 l4 = lrow[j];
        float4 n4 = nrow[j];
        const float lv[4] = {l4.x, l4.y, l4.z, l4.w};
        const float nv[4] = {n4.x, n4.y, n4.z, n4.w};
        #pragma unroll
        for (int k = 0; k < 4; k++) {
            const int idx = 4 * j + k;
            const float l = lv[k];
            amax_upd(greedy, l, idx);
            const float sc = l / safe_t;            // IEEE div, matches reference
            // online softmax on sc
            if (sc > m) {
                s = s * __expf(m - sc) + 1.0f;
                m = sc;
            } else {
                s += __expf(sc - m);
            }
            // Gumbel-max
            const float g = -logf(-logf(nv[k]));
            amax_upd(samp, sc + g, idx);
        }
    }

    // ---- block reduction ----
    __shared__ float sh_gv[32]; __shared__ int sh_gi[32];
    __shared__ float sh_sv[32]; __shared__ int sh_si[32];
    __shared__ float sh_m[32];  __shared__ float sh_s[32];
    __shared__ float fin_m, fin_inv_s;
    __shared__ int fin_tok;

    greedy = warp_amax(greedy);
    samp   = warp_amax(samp);
    warp_ms(m, s);

    if (lane == 0) {
        sh_gv[wid] = greedy.v; sh_gi[wid] = greedy.i;
        sh_sv[wid] = samp.v;   sh_si[wid] = samp.i;
        sh_m[wid]  = m;        sh_s[wid]  = s;
    }
    __syncthreads();

    if (wid == 0) {
        AMax g2; g2.v = sh_gv[lane]; g2.i = sh_gi[lane];
        AMax s2; s2.v = sh_sv[lane]; s2.i = sh_si[lane];
        float m2 = sh_m[lane], ss2 = sh_s[lane];
        g2 = warp_amax(g2);
        s2 = warp_amax(s2);
        warp_ms(m2, ss2);
        if (lane == 0) {
            fin_m = m2;
            fin_inv_s = 1.0f / ss2;
            fin_tok = (t == 0.0f) ? g2.i : s2.i;
            out[b] = (float)fin_tok;
        }
    }
    __syncthreads();

    // ---- pass 2: probs (logits reread is L2-hot for this block's row) ----
    const float mrow = fin_m;
    const float inv_s = fin_inv_s;
    const float inv_t = 1.0f / safe_t;
    for (int j = tid; j < nvec; j += NTHREADS) {
        float4 l4 = lrow[j];
        float4 p;
        p.x = __expf(l4.x * inv_t - mrow) * inv_s;
        p.y = __expf(l4.y * inv_t - mrow) * inv_s;
        p.z = __expf(l4.z * inv_t - mrow) * inv_s;
        p.w = __expf(l4.w * inv_t - mrow) * inv_s;
        prow[j] = p;
    }
}

extern "C" void kernel_launch(void* const* d_in, const int* in_sizes, int n_in,
                              void* d_out, int out_size) {
    const float* logits = (const float*)d_in[0];
    const float* temps  = (const float*)d_in[1];
    const float* noise  = (const float*)d_in[2];
    float* out = (float*)d_out;
    sampler_kernel<<<BB, NTHREADS>>>(logits, temps, noise, out);
}